// round 3
// baseline (speedup 1.0000x reference)
#include <cuda_runtime.h>

#define BATCH    2048
#define IN_F     256
#define OUT_F    512
#define OT       16     // output features per CTA
#define IC       32     // i-chunk staged per iteration
#define NTHREADS 128
#define BT       256    // batch rows per CTA (2 per thread, packed f32x2)
#define XS_STRIDE 33    // odd stride -> conflict-free column reads

typedef unsigned long long ull;

// ---- packed fp32x2 helpers (Blackwell FFMA2 path, PTX-only) ----
__device__ __forceinline__ ull pk(float a, float b) {
    ull r; asm("mov.b64 %0, {%1, %2};" : "=l"(r) : "f"(a), "f"(b)); return r;
}
__device__ __forceinline__ void unpk(ull v, float& a, float& b) {
    asm("mov.b64 {%0, %1}, %2;" : "=f"(a), "=f"(b) : "l"(v));
}
__device__ __forceinline__ ull fma2(ull a, ull b, ull c) {
    ull r; asm("fma.rn.f32x2 %0, %1, %2, %3;" : "=l"(r) : "l"(a), "l"(b), "l"(c)); return r;
}
__device__ __forceinline__ ull mul2(ull a, ull b) {
    ull r; asm("mul.rn.f32x2 %0, %1, %2;" : "=l"(r) : "l"(a), "l"(b)); return r;
}
__device__ __forceinline__ ull add2(ull a, ull b) {
    ull r; asm("add.rn.f32x2 %0, %1, %2;" : "=l"(r) : "l"(a), "l"(b)); return r;
}
__device__ __forceinline__ float frcp(float x) {
    float r; asm("rcp.approx.ftz.f32 %0, %1;" : "=f"(r) : "f"(x)); return r;
}

// Correctly-rounded x^3 (matches glibc CR powf(x,3)):
// x2h = fl(x*x) (CR x^2), x2l = exact residual; x^3 = x*x2h + x*x2l compensated.
__device__ __forceinline__ float cube_cr(float x, float x2h) {
    float x2l = fmaf(x, x, -x2h);          // exact
    float p1  = x * x2h;
    float p1e = fmaf(x, x2h, -p1);         // exact
    float r   = p1e + x * x2l;             // tiny correction
    return p1 + r;                          // faithfully CR x^3
}

// Dynamic smem layout:
//   xs: BT * XS_STRIDE floats   (x tile, padded; odd stride -> conflict-free)
//   cf: OT * IC * 16 floats     (coeffs, each value duplicated as a lane pair:
//                                [p0 p0 p1 p1 | p2 p2 p3 p3 | q0 q0 q1 q1 | q2 q2 w w])
#define XS_FLOATS (BT * XS_STRIDE)
#define CF_FLOATS (OT * IC * 16)
#define SMEM_BYTES ((XS_FLOATS + CF_FLOATS) * 4)

__global__ void __launch_bounds__(NTHREADS, 3)
kan_kernel(const float* __restrict__ x,
           const float* __restrict__ Pc,     // (O, I, 4)
           const float* __restrict__ Qc,     // (O, I, 3)
           const float* __restrict__ W,      // (O, I)
           const float* __restrict__ bias,   // (O)
           float* __restrict__ out)          // (B, O)
{
    extern __shared__ float smem[];
    float* xs = smem;
    float* cf = smem + XS_FLOATS;

    const int t     = threadIdx.x;
    const int oBase = blockIdx.x * OT;
    const int bBase = blockIdx.y * BT;
    const int b0    = bBase + t;
    const int b1    = b0 + NTHREADS;

    ull acc[OT];
#pragma unroll
    for (int o = 0; o < OT; ++o) acc[o] = 0ULL;  // bits of (0.0f, 0.0f)

    const ull ONE2 = pk(1.0f, 1.0f);
    const ull EPS2 = pk(1e-6f, 1e-6f);

    for (int c = 0; c < IN_F / IC; ++c) {
        const int i0 = c * IC;
        __syncthreads();

        // ---- stage x tile: BT rows x IC cols, coalesced global, padded smem ----
#pragma unroll 8
        for (int e = t; e < BT * IC; e += NTHREADS) {
            int bb = e >> 5;      // e / IC
            int ii = e & 31;      // e % IC
            xs[bb * XS_STRIDE + ii] = x[(bBase + bb) * IN_F + i0 + ii];
        }

        // ---- stage coefficients, duplicated as packed lane pairs ----
#pragma unroll 4
        for (int e = t; e < OT * IC; e += NTHREADS) {
            int o  = e >> 5;
            int ii = e & 31;
            int gi = (oBase + o) * IN_F + (i0 + ii);
            float4 p = *reinterpret_cast<const float4*>(Pc + (size_t)gi * 4);
            float q0 = Qc[(size_t)gi * 3 + 0];
            float q1 = Qc[(size_t)gi * 3 + 1];
            float q2 = Qc[(size_t)gi * 3 + 2];
            float w  = W[gi];
            float4* d4 = reinterpret_cast<float4*>(cf + e * 16);
            d4[0] = make_float4(p.x, p.x, p.y, p.y);
            d4[1] = make_float4(p.z, p.z, p.w, p.w);
            d4[2] = make_float4(q0, q0, q1, q1);
            d4[3] = make_float4(q2, q2, w, w);
        }
        __syncthreads();

        // ---- main compute: packed fp32x2, 2 batch rows per thread ----
#pragma unroll 1
        for (int ii = 0; ii < IC; ++ii) {
            float xa = xs[t * XS_STRIDE + ii];
            float xb = xs[(t + NTHREADS) * XS_STRIDE + ii];
            float x2a = xa * xa;                 // CR x^2
            float x2b = xb * xb;
            float x3a = cube_cr(xa, x2a);        // CR x^3
            float x3b = cube_cr(xb, x2b);
            ull X  = pk(xa, xb);
            ull X2 = pk(x2a, x2b);
            ull X3 = pk(x3a, x3b);
#pragma unroll
            for (int o = 0; o < OT; ++o) {
                const float4* c4 = reinterpret_cast<const float4*>(cf + (o * IC + ii) * 16);
                float4 v0 = c4[0];  // p0p0 p1p1
                float4 v1 = c4[1];  // p2p2 p3p3
                float4 v2 = c4[2];  // q0q0 q1q1
                float4 v3 = c4[3];  // q2q2 w w
                ull P0 = pk(v0.x, v0.y), P1 = pk(v0.z, v0.w);
                ull P2 = pk(v1.x, v1.y), P3 = pk(v1.z, v1.w);
                ull Q0 = pk(v2.x, v2.y), Q1 = pk(v2.z, v2.w);
                ull Q2 = pk(v3.x, v3.y), Wp = pk(v3.z, v3.w);

                // Numerator (association-free: only relative accuracy needed).
                // fma(p1,x,P0=0) == fl(p1*x), matching the reference's K-chain.
                ull P = fma2(P1, X, P0);
                P = fma2(P2, X2, P);
                P = fma2(P3, X3, P);

                // Denominator — MUST match reference bit-for-bit:
                //   s = fma(q2,x3, fma(q1,x2, fl(q0*x)))   (ascending-K fma chain)
                //   Q = 1 + s   (Sterbenz-exact near the pole)
                //   D = Q + 1e-6
                ull S = mul2(Q0, X);
                S = fma2(Q1, X2, S);
                S = fma2(Q2, X3, S);
                ull Qv = add2(ONE2, S);
                ull D  = add2(Qv, EPS2);

                float da, db; unpk(D, da, db);
                ull R = pk(frcp(da), frcp(db));   // relative ~1ulp: fine vs 1e-3

                acc[o] = fma2(P, R, acc[o]);      // rational contribution
                acc[o] = fma2(Wp, X, acc[o]);     // fused base GEMM term
            }
        }
    }

    // ---- epilogue: add bias, write out ----
#pragma unroll
    for (int o = 0; o < OT; ++o) {
        float a, b;
        unpk(acc[o], a, b);
        float bo = bias[oBase + o];
        out[(size_t)b0 * OUT_F + oBase + o] = a + bo;
        out[(size_t)b1 * OUT_F + oBase + o] = b + bo;
    }
}

extern "C" void kernel_launch(void* const* d_in, const int* in_sizes, int n_in,
                              void* d_out, int out_size)
{
    (void)in_sizes; (void)n_in; (void)out_size;
    const float* x    = (const float*)d_in[0];
    const float* Pc   = (const float*)d_in[1];
    const float* Qc   = (const float*)d_in[2];
    const float* W    = (const float*)d_in[3];
    const float* bias = (const float*)d_in[4];
    float* out = (float*)d_out;

    cudaFuncSetAttribute(kan_kernel, cudaFuncAttributeMaxDynamicSharedMemorySize, SMEM_BYTES);

    dim3 grid(OUT_F / OT, BATCH / BT);   // (32, 8) = 256 CTAs, single wave at occ 3
    kan_kernel<<<grid, NTHREADS, SMEM_BYTES>>>(x, Pc, Qc, W, bias, out);
}

// round 10
// speedup vs baseline: 1.0498x; 1.0498x over previous
#include <cuda_runtime.h>

#define BATCH    2048
#define IN_F     256
#define OUT_F    512
#define OT       8      // output features per CTA
#define IC       16     // i-chunk staged per iteration
#define NTHREADS 128
#define BT       512    // batch rows per CTA (4 per thread = 2 f32x2 pairs)
#define XSTR     (BT + 4)   // xs row stride in floats (mult of 4 for LDS.128; 516%32=4)

typedef unsigned long long ull;

// ---- packed fp32x2 helpers (Blackwell FFMA2 path, PTX-only) ----
__device__ __forceinline__ ull pk(float a, float b) {
    ull r; asm("mov.b64 %0, {%1, %2};" : "=l"(r) : "f"(a), "f"(b)); return r;
}
__device__ __forceinline__ void unpk(ull v, float& a, float& b) {
    asm("mov.b64 {%0, %1}, %2;" : "=f"(a), "=f"(b) : "l"(v));
}
__device__ __forceinline__ ull fma2(ull a, ull b, ull c) {
    ull r; asm("fma.rn.f32x2 %0, %1, %2, %3;" : "=l"(r) : "l"(a), "l"(b), "l"(c)); return r;
}
__device__ __forceinline__ ull mul2(ull a, ull b) {
    ull r; asm("mul.rn.f32x2 %0, %1, %2;" : "=l"(r) : "l"(a), "l"(b)); return r;
}
__device__ __forceinline__ ull add2(ull a, ull b) {
    ull r; asm("add.rn.f32x2 %0, %1, %2;" : "=l"(r) : "l"(a), "l"(b)); return r;
}
__device__ __forceinline__ float frcp(float x) {
    float r; asm("rcp.approx.ftz.f32 %0, %1;" : "=f"(r) : "f"(x)); return r;
}

// Correctly-rounded x^3 (frozen numerics — matches reference powf(x,3)):
__device__ __forceinline__ float cube_cr(float x, float x2h) {
    float x2l = fmaf(x, x, -x2h);          // exact residual of x^2
    float p1  = x * x2h;
    float p1e = fmaf(x, x2h, -p1);         // exact
    float r   = p1e + x * x2l;
    return p1 + r;
}

// Dynamic smem layout:
//   xs: IC rows x XSTR floats  -- x tile TRANSPOSED [ii][b]; inner loop reads
//       each thread's 4 consecutive b's as one LDS.128 (conflict-free per 1/4-warp)
//   cf: OT * IC * 16 floats    -- coeffs duplicated as lane pairs:
//       [p0 p0 p1 p1 | p2 p2 p3 p3 | q0 q0 q1 q1 | q2 q2 w w]
#define XS_FLOATS (IC * XSTR)
#define CF_FLOATS (OT * IC * 16)
#define SMEM_BYTES ((XS_FLOATS + CF_FLOATS) * 4)

__global__ void __launch_bounds__(NTHREADS, 4)
kan_kernel(const float* __restrict__ x,
           const float* __restrict__ Pc,     // (O, I, 4)
           const float* __restrict__ Qc,     // (O, I, 3)
           const float* __restrict__ W,      // (O, I)
           const float* __restrict__ bias,   // (O)
           float* __restrict__ out)          // (B, O)
{
    extern __shared__ float smem[];
    float* xs = smem;
    float* cf = smem + XS_FLOATS;

    const int t     = threadIdx.x;
    const int oBase = blockIdx.x * OT;
    const int bBase = blockIdx.y * BT;
    const int myB   = bBase + 4 * t;          // 4 consecutive batch rows per thread

    ull acc01[OT], acc23[OT];                 // accumulators for pairs (b0,b1),(b2,b3)
#pragma unroll
    for (int o = 0; o < OT; ++o) { acc01[o] = 0ULL; acc23[o] = 0ULL; }

    const ull ONE2 = pk(1.0f, 1.0f);
    const ull EPS2 = pk(1e-6f, 1e-6f);

    for (int c = 0; c < IN_F / IC; ++c) {
        const int i0 = c * IC;
        __syncthreads();

        // ---- stage x tile transposed: read float4 along i, scatter to xs[ii][b] ----
        // BT*IC/4 = 2048 float4 elems / 128 threads = 16 vector loads per thread
#pragma unroll 4
        for (int e4 = t; e4 < BT * IC / 4; e4 += NTHREADS) {
            int bb = e4 >> 2;                 // batch row (IC/4 = 4 vecs per row)
            int ci = e4 & 3;                  // which float4 within the IC chunk
            float4 v = *reinterpret_cast<const float4*>(
                x + (size_t)(bBase + bb) * IN_F + i0 + 4 * ci);
            xs[(4 * ci + 0) * XSTR + bb] = v.x;
            xs[(4 * ci + 1) * XSTR + bb] = v.y;
            xs[(4 * ci + 2) * XSTR + bb] = v.z;
            xs[(4 * ci + 3) * XSTR + bb] = v.w;
        }

        // ---- stage coefficients (OT*IC = 128 = exactly 1 per thread) ----
        {
            int o  = t >> 4;                  // t / IC
            int ii = t & 15;                  // t % IC
            int gi = (oBase + o) * IN_F + (i0 + ii);
            float4 p = *reinterpret_cast<const float4*>(Pc + (size_t)gi * 4);
            float q0 = Qc[(size_t)gi * 3 + 0];
            float q1 = Qc[(size_t)gi * 3 + 1];
            float q2 = Qc[(size_t)gi * 3 + 2];
            float w  = W[gi];
            float4* d4 = reinterpret_cast<float4*>(cf + t * 16);
            d4[0] = make_float4(p.x, p.x, p.y, p.y);
            d4[1] = make_float4(p.z, p.z, p.w, p.w);
            d4[2] = make_float4(q0, q0, q1, q1);
            d4[3] = make_float4(q2, q2, w, w);
        }
        __syncthreads();

        // ---- main compute: 4 batch rows per thread, packed f32x2 ----
#pragma unroll 1
        for (int ii = 0; ii < IC; ++ii) {
            float4 xv = *reinterpret_cast<const float4*>(xs + ii * XSTR + 4 * t);
            float x2a = xv.x * xv.x, x2b = xv.y * xv.y;
            float x2c = xv.z * xv.z, x2d = xv.w * xv.w;
            float x3a = cube_cr(xv.x, x2a), x3b = cube_cr(xv.y, x2b);
            float x3c = cube_cr(xv.z, x2c), x3d = cube_cr(xv.w, x2d);
            ull Xp  = pk(xv.x, xv.y), Xq  = pk(xv.z, xv.w);
            ull X2p = pk(x2a, x2b),   X2q = pk(x2c, x2d);
            ull X3p = pk(x3a, x3b),   X3q = pk(x3c, x3d);
#pragma unroll
            for (int o = 0; o < OT; ++o) {
                const float4* c4 = reinterpret_cast<const float4*>(cf + (o * IC + ii) * 16);
                float4 v0 = c4[0];  // p0p0 p1p1
                float4 v1 = c4[1];  // p2p2 p3p3
                float4 v2 = c4[2];  // q0q0 q1q1
                float4 v3 = c4[3];  // q2q2 w w
                ull P0 = pk(v0.x, v0.y), P1 = pk(v0.z, v0.w);
                ull P2 = pk(v1.x, v1.y), P3 = pk(v1.z, v1.w);
                ull Q0 = pk(v2.x, v2.y), Q1 = pk(v2.z, v2.w);
                ull Q2 = pk(v3.x, v3.y), Wp = pk(v3.z, v3.w);

                // ---- pair 0: (b0, b1) ----  [numerics frozen: do not reassociate]
                ull Pa = fma2(P1, Xp, P0);
                Pa = fma2(P2, X2p, Pa);
                Pa = fma2(P3, X3p, Pa);
                ull Sa = mul2(Q0, Xp);
                Sa = fma2(Q1, X2p, Sa);
                Sa = fma2(Q2, X3p, Sa);
                ull Da = add2(add2(ONE2, Sa), EPS2);
                float d0, d1; unpk(Da, d0, d1);
                ull Ra = pk(frcp(d0), frcp(d1));
                acc01[o] = fma2(Pa, Ra, acc01[o]);
                acc01[o] = fma2(Wp, Xp, acc01[o]);

                // ---- pair 1: (b2, b3) ----
                ull Pb = fma2(P1, Xq, P0);
                Pb = fma2(P2, X2q, Pb);
                Pb = fma2(P3, X3q, Pb);
                ull Sb = mul2(Q0, Xq);
                Sb = fma2(Q1, X2q, Sb);
                Sb = fma2(Q2, X3q, Sb);
                ull Db = add2(add2(ONE2, Sb), EPS2);
                float d2, d3; unpk(Db, d2, d3);
                ull Rb = pk(frcp(d2), frcp(d3));
                acc23[o] = fma2(Pb, Rb, acc23[o]);
                acc23[o] = fma2(Wp, Xq, acc23[o]);
            }
        }
    }

    // ---- epilogue: add bias, vectorized stores (8 consecutive o's per b) ----
    float bo[OT];
#pragma unroll
    for (int o = 0; o < OT; ++o) bo[o] = bias[oBase + o];

#pragma unroll
    for (int b = 0; b < 4; ++b) {
        float v[OT];
#pragma unroll
        for (int o = 0; o < OT; ++o) {
            float a0, a1;
            if (b < 2) { unpk(acc01[o], a0, a1); v[o] = (b == 0 ? a0 : a1) + bo[o]; }
            else       { unpk(acc23[o], a0, a1); v[o] = (b == 2 ? a0 : a1) + bo[o]; }
        }
        float* dst = out + (size_t)(myB + b) * OUT_F + oBase;
        reinterpret_cast<float4*>(dst)[0] = make_float4(v[0], v[1], v[2], v[3]);
        reinterpret_cast<float4*>(dst)[1] = make_float4(v[4], v[5], v[6], v[7]);
    }
}

extern "C" void kernel_launch(void* const* d_in, const int* in_sizes, int n_in,
                              void* d_out, int out_size)
{
    (void)in_sizes; (void)n_in; (void)out_size;
    const float* x    = (const float*)d_in[0];
    const float* Pc   = (const float*)d_in[1];
    const float* Qc   = (const float*)d_in[2];
    const float* W    = (const float*)d_in[3];
    const float* bias = (const float*)d_in[4];
    float* out = (float*)d_out;

    cudaFuncSetAttribute(kan_kernel, cudaFuncAttributeMaxDynamicSharedMemorySize, SMEM_BYTES);

    dim3 grid(OUT_F / OT, BATCH / BT);   // (64, 4) = 256 CTAs
    kan_kernel<<<grid, NTHREADS, SMEM_BYTES>>>(x, Pc, Qc, W, bias, out);
}

// round 13
// speedup vs baseline: 1.0971x; 1.0451x over previous
#include <cuda_runtime.h>

#define BATCH    2048
#define IN_F     256
#define OUT_F    512
#define OT       8      // output features per CTA
#define IC       16     // i-chunk staged per iteration
#define NTHREADS 256    // 2 warpgroups; each handles one i-half
#define IHALF    128    // IN_F / 2, per warpgroup
#define BT       512    // batch rows per CTA (4 per thread-of-warpgroup)
#define XSTR     (BT + 4)   // xs row stride in floats (mult of 4 for LDS.128)

typedef unsigned long long ull;

// ---- packed fp32x2 helpers (Blackwell FFMA2 path, PTX-only) ----
__device__ __forceinline__ ull pk(float a, float b) {
    ull r; asm("mov.b64 %0, {%1, %2};" : "=l"(r) : "f"(a), "f"(b)); return r;
}
__device__ __forceinline__ void unpk(ull v, float& a, float& b) {
    asm("mov.b64 {%0, %1}, %2;" : "=f"(a), "=f"(b) : "l"(v));
}
__device__ __forceinline__ ull fma2(ull a, ull b, ull c) {
    ull r; asm("fma.rn.f32x2 %0, %1, %2, %3;" : "=l"(r) : "l"(a), "l"(b), "l"(c)); return r;
}
__device__ __forceinline__ ull mul2(ull a, ull b) {
    ull r; asm("mul.rn.f32x2 %0, %1, %2;" : "=l"(r) : "l"(a), "l"(b)); return r;
}
__device__ __forceinline__ ull add2(ull a, ull b) {
    ull r; asm("add.rn.f32x2 %0, %1, %2;" : "=l"(r) : "l"(a), "l"(b)); return r;
}
__device__ __forceinline__ float frcp(float x) {
    float r; asm("rcp.approx.ftz.f32 %0, %1;" : "=f"(r) : "f"(x)); return r;
}

// Correctly-rounded x^3 (frozen numerics — matches reference powf(x,3)):
__device__ __forceinline__ float cube_cr(float x, float x2h) {
    float x2l = fmaf(x, x, -x2h);          // exact residual of x^2
    float p1  = x * x2h;
    float p1e = fmaf(x, x2h, -p1);         // exact
    float r   = p1e + x * x2l;
    return p1 + r;
}

// Dynamic smem layout (per-warpgroup regions, wg = 0/1):
//   xs[wg]: IC x XSTR floats  -- transposed x tile [ii][b] for that wg's i-half
//   cf[wg]: OT * IC * 16 floats -- coeffs as duplicated lane pairs
// Epilogue reuses the xs area as a 16 KB ull scratch for the wg1 partials.
#define XS_FLOATS (IC * XSTR)
#define CF_FLOATS (OT * IC * 16)
#define SMEM_BYTES ((2 * XS_FLOATS + 2 * CF_FLOATS) * 4)

__global__ void __launch_bounds__(NTHREADS, 2)
kan_kernel(const float* __restrict__ x,
           const float* __restrict__ Pc,     // (O, I, 4)
           const float* __restrict__ Qc,     // (O, I, 3)
           const float* __restrict__ W,      // (O, I)
           const float* __restrict__ bias,   // (O)
           float* __restrict__ out)          // (B, O)
{
    extern __shared__ float smem[];

    const int t     = threadIdx.x;
    const int wg    = t >> 7;                 // warpgroup: 0 or 1
    const int wt    = t & 127;                // thread id within warpgroup
    const int iBase = wg * IHALF;             // this wg's i-half

    float* xs = smem + wg * XS_FLOATS;
    float* cf = smem + 2 * XS_FLOATS + wg * CF_FLOATS;

    const int oBase = blockIdx.x * OT;
    const int bBase = blockIdx.y * BT;
    const int myB   = bBase + 4 * wt;         // 4 consecutive batch rows per thread

    ull acc01[OT], acc23[OT];                 // pairs (b0,b1),(b2,b3)
#pragma unroll
    for (int o = 0; o < OT; ++o) { acc01[o] = 0ULL; acc23[o] = 0ULL; }

    const ull ONE2 = pk(1.0f, 1.0f);
    const ull EPS2 = pk(1e-6f, 1e-6f);

    for (int c = 0; c < IHALF / IC; ++c) {    // 8 chunks over this wg's 128 i's
        const int i0 = iBase + c * IC;
        __syncthreads();

        // ---- stage x tile transposed: BT x IC, float4 along i, scatter to xs[ii][b] ----
#pragma unroll 4
        for (int e4 = wt; e4 < BT * IC / 4; e4 += 128) {
            int bb = e4 >> 2;                 // batch row (IC/4 = 4 vecs per row)
            int ci = e4 & 3;
            float4 v = *reinterpret_cast<const float4*>(
                x + (size_t)(bBase + bb) * IN_F + i0 + 4 * ci);
            xs[(4 * ci + 0) * XSTR + bb] = v.x;
            xs[(4 * ci + 1) * XSTR + bb] = v.y;
            xs[(4 * ci + 2) * XSTR + bb] = v.z;
            xs[(4 * ci + 3) * XSTR + bb] = v.w;
        }

        // ---- stage coefficients (OT*IC = 128 = one per wg thread) ----
        {
            int o  = wt >> 4;                 // wt / IC
            int ii = wt & 15;                 // wt % IC
            int gi = (oBase + o) * IN_F + (i0 + ii);
            float4 p = *reinterpret_cast<const float4*>(Pc + (size_t)gi * 4);
            float q0 = Qc[(size_t)gi * 3 + 0];
            float q1 = Qc[(size_t)gi * 3 + 1];
            float q2 = Qc[(size_t)gi * 3 + 2];
            float w  = W[gi];
            float4* d4 = reinterpret_cast<float4*>(cf + wt * 16);
            d4[0] = make_float4(p.x, p.x, p.y, p.y);
            d4[1] = make_float4(p.z, p.z, p.w, p.w);
            d4[2] = make_float4(q0, q0, q1, q1);
            d4[3] = make_float4(q2, q2, w, w);
        }
        __syncthreads();

        // ---- main compute: 4 batch rows per thread, packed f32x2 ----
#pragma unroll 1
        for (int ii = 0; ii < IC; ++ii) {
            float4 xv = *reinterpret_cast<const float4*>(xs + ii * XSTR + 4 * wt);
            float x2a = xv.x * xv.x, x2b = xv.y * xv.y;
            float x2c = xv.z * xv.z, x2d = xv.w * xv.w;
            float x3a = cube_cr(xv.x, x2a), x3b = cube_cr(xv.y, x2b);
            float x3c = cube_cr(xv.z, x2c), x3d = cube_cr(xv.w, x2d);
            ull Xp  = pk(xv.x, xv.y), Xq  = pk(xv.z, xv.w);
            ull X2p = pk(x2a, x2b),   X2q = pk(x2c, x2d);
            ull X3p = pk(x3a, x3b),   X3q = pk(x3c, x3d);
#pragma unroll
            for (int o = 0; o < OT; ++o) {
                const float4* c4 = reinterpret_cast<const float4*>(cf + (o * IC + ii) * 16);
                float4 v0 = c4[0];  // p0p0 p1p1
                float4 v1 = c4[1];  // p2p2 p3p3
                float4 v2 = c4[2];  // q0q0 q1q1
                float4 v3 = c4[3];  // q2q2 w w
                ull P0 = pk(v0.x, v0.y), P1 = pk(v0.z, v0.w);
                ull P2 = pk(v1.x, v1.y), P3 = pk(v1.z, v1.w);
                ull Q0 = pk(v2.x, v2.y), Q1 = pk(v2.z, v2.w);
                ull Q2 = pk(v3.x, v3.y), Wp = pk(v3.z, v3.w);

                // ---- pair 0: (b0, b1) ----  [numerics frozen: do not reassociate]
                ull Pa = fma2(P1, Xp, P0);
                Pa = fma2(P2, X2p, Pa);
                Pa = fma2(P3, X3p, Pa);
                ull Sa = mul2(Q0, Xp);
                Sa = fma2(Q1, X2p, Sa);
                Sa = fma2(Q2, X3p, Sa);
                ull Da = add2(add2(ONE2, Sa), EPS2);
                float d0, d1; unpk(Da, d0, d1);
                ull Ra = pk(frcp(d0), frcp(d1));
                acc01[o] = fma2(Pa, Ra, acc01[o]);
                acc01[o] = fma2(Wp, Xp, acc01[o]);

                // ---- pair 1: (b2, b3) ----
                ull Pb = fma2(P1, Xq, P0);
                Pb = fma2(P2, X2q, Pb);
                Pb = fma2(P3, X3q, Pb);
                ull Sb = mul2(Q0, Xq);
                Sb = fma2(Q1, X2q, Sb);
                Sb = fma2(Q2, X3q, Sb);
                ull Db = add2(add2(ONE2, Sb), EPS2);
                float d2, d3; unpk(Db, d2, d3);
                ull Rb = pk(frcp(d2), frcp(d3));
                acc23[o] = fma2(Pb, Rb, acc23[o]);
                acc23[o] = fma2(Wp, Xq, acc23[o]);
            }
        }
    }

    // ---- combine the two i-halves (deterministic intra-CTA reduction) ----
    __syncthreads();                          // compute done; xs area reusable
    ull* scratch = reinterpret_cast<ull*>(smem);   // 16 KB needed, 80 KB available

    if (wg == 1) {
        // k-major layout: scratch[k*128 + wt] -> 2-way bank conflict only
#pragma unroll
        for (int o = 0; o < OT; ++o) {
            scratch[(2 * o + 0) * 128 + wt] = acc01[o];
            scratch[(2 * o + 1) * 128 + wt] = acc23[o];
        }
    }
    __syncthreads();

    if (wg == 0) {
        float bo[OT];
#pragma unroll
        for (int o = 0; o < OT; ++o) bo[o] = bias[oBase + o];

#pragma unroll
        for (int o = 0; o < OT; ++o) {
            acc01[o] = add2(acc01[o], scratch[(2 * o + 0) * 128 + wt]);
            acc23[o] = add2(acc23[o], scratch[(2 * o + 1) * 128 + wt]);
        }

#pragma unroll
        for (int b = 0; b < 4; ++b) {
            float v[OT];
#pragma unroll
            for (int o = 0; o < OT; ++o) {
                float a0, a1;
                if (b < 2) { unpk(acc01[o], a0, a1); v[o] = (b == 0 ? a0 : a1) + bo[o]; }
                else       { unpk(acc23[o], a0, a1); v[o] = (b == 2 ? a0 : a1) + bo[o]; }
            }
            float* dst = out + (size_t)(myB + b) * OUT_F + oBase;
            reinterpret_cast<float4*>(dst)[0] = make_float4(v[0], v[1], v[2], v[3]);
            reinterpret_cast<float4*>(dst)[1] = make_float4(v[4], v[5], v[6], v[7]);
        }
    }
}

extern "C" void kernel_launch(void* const* d_in, const int* in_sizes, int n_in,
                              void* d_out, int out_size)
{
    (void)in_sizes; (void)n_in; (void)out_size;
    const float* x    = (const float*)d_in[0];
    const float* Pc   = (const float*)d_in[1];
    const float* Qc   = (const float*)d_in[2];
    const float* W    = (const float*)d_in[3];
    const float* bias = (const float*)d_in[4];
    float* out = (float*)d_out;

    cudaFuncSetAttribute(kan_kernel, cudaFuncAttributeMaxDynamicSharedMemorySize, SMEM_BYTES);

    dim3 grid(OUT_F / OT, BATCH / BT);   // (64, 4) = 256 CTAs x 8 warps, single wave
    kan_kernel<<<grid, NTHREADS, SMEM_BYTES>>>(x, Pc, Qc, W, bias, out);
}